// round 15
// baseline (speedup 1.0000x reference)
#include <cuda_runtime.h>
#include <cuda_fp16.h>
#include <math.h>

#define B_   2
#define G_   8
#define L_   576
#define D_   32
#define NTOK 9216
#define NT32 (NTOK * 32)
#define NTILES 144
#define LOG2E 1.4426950408889634f

// Scratch (__device__ globals; allocation-free rule)
__device__ float    g_Q[NT32];
__device__ unsigned g_Kq[NT32 / 2];   // f16 K hi: [tile][kn 64][4 uint4: t*4 + {b0k0,b1k0,b0k1,b1k1}]
__device__ unsigned g_Vp[NT32];       // tf32 V: [tile][kp 32][feat 32] uint2
__device__ float    g_qnorm2[NTOK];
__device__ int      g_kmax2;

__device__ __forceinline__ unsigned f2tf32(float x) {
    unsigned r;
    asm("cvt.rna.tf32.f32 %0, %1;" : "=r"(r) : "f"(x));
    return r;
}
__device__ __forceinline__ void split2_f16(float x0, float x1,
                                           unsigned& hi, unsigned& lo) {
    __half h0 = __float2half_rn(x0), h1 = __float2half_rn(x1);
    __half l0 = __float2half_rn(x0 - __half2float(h0));
    __half l1 = __float2half_rn(x1 - __half2float(h1));
    hi = ((unsigned)__half_as_ushort(h1) << 16) | __half_as_ushort(h0);
    lo = ((unsigned)__half_as_ushort(l1) << 16) | __half_as_ushort(l0);
}
__device__ __forceinline__ void mma_f16(float c[4], const unsigned a[4],
                                        unsigned b0, unsigned b1) {
    asm volatile(
        "mma.sync.aligned.m16n8k16.row.col.f32.f16.f16.f32 "
        "{%0,%1,%2,%3}, {%4,%5,%6,%7}, {%8,%9}, {%0,%1,%2,%3};"
        : "+f"(c[0]), "+f"(c[1]), "+f"(c[2]), "+f"(c[3])
        : "r"(a[0]), "r"(a[1]), "r"(a[2]), "r"(a[3]), "r"(b0), "r"(b1));
}
__device__ __forceinline__ void mma_tf32(float c[4], const unsigned a[4],
                                         unsigned b0, unsigned b1) {
    asm volatile(
        "mma.sync.aligned.m16n8k8.row.col.f32.tf32.tf32.f32 "
        "{%0,%1,%2,%3}, {%4,%5,%6,%7}, {%8,%9}, {%0,%1,%2,%3};"
        : "+f"(c[0]), "+f"(c[1]), "+f"(c[2]), "+f"(c[3])
        : "r"(a[0]), "r"(a[1]), "r"(a[2]), "r"(a[3]), "r"(b0), "r"(b1));
}

// ---------------------------------------------------------------------------
// Kernel 1: grouped 1x1 conv, one matrix per blockIdx.z.
// Q scaled + row norms. K(+PE): f16 HI ONLY, packed per-key so one uint4
// feeds both k-chunks; built in smem, written out coalesced.
// V -> tf32 paired layout.
// ---------------------------------------------------------------------------
__global__ void __launch_bounds__(256) qkv_kernel(
    const float* __restrict__ x,
    const float* __restrict__ wq,
    const float* __restrict__ wk,
    const float* __restrict__ wv)
{
    const int bh = blockIdx.x;
    const int b  = bh >> 3;
    const int h  = bh & 7;
    const int l0 = blockIdx.y * 64;
    const int m  = blockIdx.z;

    __shared__ float xs[32][64];
    __shared__ __half Ksm[64][32];   // K hi tile image (m==1 only), 4KB

    const int tid = threadIdx.x;
    const float* xbase = x + ((size_t)(b * 256 + h * 32)) * L_ + l0;
    for (int i = tid; i < 32 * 64; i += 256) {
        int dd = i >> 6, ll = i & 63;
        xs[dd][ll] = xbase[dd * L_ + ll];
    }
    __syncthreads();

    const int o    = tid & 31;
    const int lg   = (tid >> 5) * 8;
    const int c    = h * 32 + o;
    const int nbase = bh * L_ + l0 + lg;
    const int tile = bh * 9 + blockIdx.y;

    const float* w = (m == 0 ? wq : (m == 1 ? wk : wv)) + (size_t)c * 32;
    float acc[8];
    #pragma unroll
    for (int e = 0; e < 8; e++) acc[e] = 0.f;

    #pragma unroll
    for (int dd = 0; dd < 32; dd++) {
        float wv_ = w[dd];
        float4 a  = *(const float4*)&xs[dd][lg];
        float4 a2 = *(const float4*)&xs[dd][lg + 4];
        acc[0] = fmaf(wv_, a.x,  acc[0]);
        acc[1] = fmaf(wv_, a.y,  acc[1]);
        acc[2] = fmaf(wv_, a.z,  acc[2]);
        acc[3] = fmaf(wv_, a.w,  acc[3]);
        acc[4] = fmaf(wv_, a2.x, acc[4]);
        acc[5] = fmaf(wv_, a2.y, acc[5]);
        acc[6] = fmaf(wv_, a2.z, acc[6]);
        acc[7] = fmaf(wv_, a2.w, acc[7]);
    }

    if (m == 0) {
        const float scale = 0.17677669529663688f;  // 1/sqrt(32)
        #pragma unroll
        for (int e = 0; e < 8; e++) {
            float val = acc[e] * scale;
            g_Q[(size_t)(nbase + e) * 32 + o] = val;
            float sq = val * val;
            #pragma unroll
            for (int off = 16; off > 0; off >>= 1)
                sq += __shfl_xor_sync(0xffffffffu, sq, off);
            if (o == 0) g_qnorm2[nbase + e] = sq;
        }
    } else if (m == 1) {
        int ieven = c & ~1;
        float tf = (-9.210340371976184f * (float)ieven) * (1.0f / 256.0f);
        float invf = (float)exp((double)tf);
        double s0d, c0d, sid, cid;
        sincos((double)invf * (double)(l0 + lg), &s0d, &c0d);
        sincos((double)invf, &sid, &cid);
        float sB = (float)s0d, cB = (float)c0d;
        float sI = (float)sid, cI = (float)cid;
        // half index within key row: t*8 + ks*4 + breg*2 + hw
        const int ksq  = o >> 4;
        const int rr   = o & 15;
        const int tq   = (rr & 7) >> 1;
        const int hw   = rr & 1;
        const int breg = rr >> 3;
        const int hbase = tq * 8 + ksq * 4 + breg * 2 + hw;
        float kmax_local = 0.f;
        #pragma unroll
        for (int e = 0; e < 8; e++) {
            float pe = (c & 1) ? cB : sB;
            float sn = sB * cI + cB * sI;
            float cn = cB * cI - sB * sI;
            sB = sn; cB = cn;
            float val = acc[e] + pe;
            int j = lg + e;
            int kn = (j & 56) + 2 * (j & 3) + ((j >> 2) & 1);  // sigma
            Ksm[kn][hbase] = __float2half_rn(val);
            float sq = val * val;
            #pragma unroll
            for (int off = 16; off > 0; off >>= 1)
                sq += __shfl_xor_sync(0xffffffffu, sq, off);
            kmax_local = fmaxf(kmax_local, sq);
        }
        if (o == 0) atomicMax(&g_kmax2, __float_as_int(kmax_local));
        __syncthreads();
        // coalesced write-out: 1024 words = 1 uint4 per thread
        const unsigned* src = (const unsigned*)Ksm;
        unsigned* dst = g_Kq + (size_t)tile * 1024;
        *(uint4*)&dst[tid * 4] = *(const uint4*)&src[tid * 4];
    } else {
        #pragma unroll
        for (int e = 0; e < 8; e++) {
            int j = lg + e;
            int kp   = ((j >> 3) << 2) + (j & 3);
            int slot = (j >> 2) & 1;
            g_Vp[(size_t)tile * 2048 + (size_t)(kp * 32 + o) * 2 + slot] =
                f2tf32(acc[e]);
        }
    }
}

// ---------------------------------------------------------------------------
// Kernel 2: flash attention. 144 blocks x 256 threads (8 warps = 4mw x 2nw).
// TWO key-tiles per iteration (72 iters), quad-buffered K/V, 1 barrier/iter.
// QK: K f16-hi only; Q 2-way split -> 2 MMAs per k-chunk, one LDS.128 per nt
// feeds both chunks. PV tf32, P in regs (sigma trick).
// ---------------------------------------------------------------------------
#define KSTR  16       // words per key row, exact (bank-verified)
#define KBUF  1024     // 64 * 16 words
#define VSTRU 36
#define VBUF  2304     // 32 * 36 * 2 words
#define QSTR  36
#define OFF_K 0
#define OFF_V (4 * KBUF)
#define OFF_Q (OFF_V + 4 * VBUF)
#define OFF_O (OFF_Q + 64 * QSTR)
#define OFF_R (OFF_O + 2048)
#define SMEM_WORDS (OFF_R + 128)
#define SMEM_BYTES (SMEM_WORDS * 4)

__global__ void __launch_bounds__(256) attn_kernel(float* __restrict__ out)
{
    extern __shared__ unsigned smem[];
    unsigned* Ks  = smem + OFF_K;
    unsigned* Vs  = smem + OFF_V;
    float*    Qst = (float*)(smem + OFF_Q);
    float*    Osm = (float*)(smem + OFF_O);
    float*    red = (float*)(smem + OFF_R);

    const int tid  = threadIdx.x;
    const int lane = tid & 31;
    const int w    = tid >> 5;
    const int mw   = w >> 1, nw = w & 1;
    const int g    = lane >> 2, t = lane & 3;
    const int q0   = blockIdx.x * 64;
    const int r0   = 16 * mw + g;

    // ---- stage Q, build f16 split A-frags ----
    for (int i = tid; i < 512; i += 256) {
        int r = i >> 3, c = (i & 7) * 4;
        *(float4*)&Qst[r * QSTR + c] =
            *(const float4*)&g_Q[(size_t)(q0 + r) * 32 + c];
    }
    __syncthreads();

    unsigned qh[2][4], ql[2][4];
    #pragma unroll
    for (int ks = 0; ks < 2; ks++) {
        int d0 = 16 * ks + 2 * t;
        split2_f16(Qst[r0 * QSTR + d0],           Qst[r0 * QSTR + d0 + 1],
                   qh[ks][0], ql[ks][0]);
        split2_f16(Qst[(r0 + 8) * QSTR + d0],     Qst[(r0 + 8) * QSTR + d0 + 1],
                   qh[ks][1], ql[ks][1]);
        split2_f16(Qst[r0 * QSTR + d0 + 8],       Qst[r0 * QSTR + d0 + 9],
                   qh[ks][2], ql[ks][2]);
        split2_f16(Qst[(r0 + 8) * QSTR + d0 + 8], Qst[(r0 + 8) * QSTR + d0 + 9],
                   qh[ks][3], ql[ks][3]);
    }

    const float kmax2 = __int_as_float(g_kmax2);
    const float Ml0 = sqrtf(g_qnorm2[q0 + r0]     * kmax2) * LOG2E;
    const float Ml1 = sqrtf(g_qnorm2[q0 + r0 + 8] * kmax2) * LOG2E;

    // ---- prefetch tiles 0,1 into buffers 0,1 ----
    #pragma unroll
    for (int p = 0; p < 2; p++) {
        unsigned* Kb = Ks + p * KBUF;
        unsigned* Vb = Vs + p * VBUF;
        // K: 1024 words -> 1 uint4/thread (flat copy; image == smem layout)
        *(uint4*)&Kb[tid * 4] =
            *(const uint4*)&g_Kq[(size_t)p * 1024 + (size_t)tid * 4];
        // V: 2048 words -> 2 uint4/thread
        #pragma unroll
        for (int j = 0; j < 2; j++) {
            int u = tid + 256 * j;
            uint4 vv = *(const uint4*)&g_Vp[(size_t)p * 2048 + (size_t)u * 4];
            int kp = u >> 4, fp = u & 15;
            *(uint4*)&Vb[kp * (2 * VSTRU) + fp * 4] = vv;
        }
    }
    __syncthreads();

    float o[4][4];
    #pragma unroll
    for (int i = 0; i < 4; i++)
        #pragma unroll
        for (int jj = 0; jj < 4; jj++) o[i][jj] = 0.f;
    float lp0 = 0.f, lp1 = 0.f;

    for (int it = 0; it < NTILES / 2; it++) {
        const int t0 = 2 * it;
        const unsigned* Kc0 = Ks + (t0 & 3) * KBUF;
        const unsigned* Kc1 = Ks + ((t0 + 1) & 3) * KBUF;
        const unsigned* Vc0 = Vs + (t0 & 3) * VBUF;
        const unsigned* Vc1 = Vs + ((t0 + 1) & 3) * VBUF;

        // ---- LDG tiles t0+2, t0+3 ----
        uint4 nk[2], nv[2][2];
        const bool has_next = (t0 + 2 < NTILES);
        if (has_next) {
            #pragma unroll
            for (int p = 0; p < 2; p++) {
                nk[p] = *(const uint4*)&g_Kq[(size_t)(t0 + 2 + p) * 1024 +
                                             (size_t)tid * 4];
                size_t vb = (size_t)(t0 + 2 + p) * 2048;
                #pragma unroll
                for (int j = 0; j < 2; j++) {
                    int u = tid + 256 * j;
                    nv[p][j] = *(const uint4*)&g_Vp[vb + (size_t)u * 4];
                }
            }
        }

        // ---- S for both tiles: one LDS.128 per nt feeds both k-chunks ----
        float S0[4][4], S1[4][4];
        #pragma unroll
        for (int i = 0; i < 4; i++)
            #pragma unroll
            for (int jj = 0; jj < 4; jj++) { S0[i][jj] = 0.f; S1[i][jj] = 0.f; }

        #pragma unroll
        for (int nt = 0; nt < 4; nt++) {
            int kn = 32 * nw + 8 * nt + g;
            uint4 bf0 = *(const uint4*)&Kc0[kn * KSTR + 4 * t];
            uint4 bf1 = *(const uint4*)&Kc1[kn * KSTR + 4 * t];
            mma_f16(S0[nt], qh[0], bf0.x, bf0.y);
            mma_f16(S1[nt], qh[0], bf1.x, bf1.y);
            mma_f16(S0[nt], ql[0], bf0.x, bf0.y);
            mma_f16(S1[nt], ql[0], bf1.x, bf1.y);
            mma_f16(S0[nt], qh[1], bf0.z, bf0.w);
            mma_f16(S1[nt], qh[1], bf1.z, bf1.w);
            mma_f16(S0[nt], ql[1], bf0.z, bf0.w);
            mma_f16(S1[nt], ql[1], bf1.z, bf1.w);
        }

        // ---- P = exp2(S*log2e - M) in-place; accumulate l ----
        #pragma unroll
        for (int nt = 0; nt < 4; nt++) {
            S0[nt][0] = exp2f(fmaf(S0[nt][0], LOG2E, -Ml0));
            S0[nt][1] = exp2f(fmaf(S0[nt][1], LOG2E, -Ml0));
            S0[nt][2] = exp2f(fmaf(S0[nt][2], LOG2E, -Ml1));
            S0[nt][3] = exp2f(fmaf(S0[nt][3], LOG2E, -Ml1));
            S1[nt][0] = exp2f(fmaf(S1[nt][0], LOG2E, -Ml0));
            S1[nt][1] = exp2f(fmaf(S1[nt][1], LOG2E, -Ml0));
            S1[nt][2] = exp2f(fmaf(S1[nt][2], LOG2E, -Ml1));
            S1[nt][3] = exp2f(fmaf(S1[nt][3], LOG2E, -Ml1));
            lp0 += S0[nt][0] + S0[nt][1] + S1[nt][0] + S1[nt][1];
            lp1 += S0[nt][2] + S0[nt][3] + S1[nt][2] + S1[nt][3];
        }

        // ---- O += P V for both tiles (tf32 single-pass) ----
        #pragma unroll
        for (int ks = 0; ks < 4; ks++) {
            unsigned a0[4], a1[4];
            a0[0] = f2tf32(S0[ks][0]);  a1[0] = f2tf32(S1[ks][0]);
            a0[1] = f2tf32(S0[ks][2]);  a1[1] = f2tf32(S1[ks][2]);
            a0[2] = f2tf32(S0[ks][1]);  a1[2] = f2tf32(S1[ks][1]);
            a0[3] = f2tf32(S0[ks][3]);  a1[3] = f2tf32(S1[ks][3]);
            int kp = (4 * nw + ks) * 4 + t;
            #pragma unroll
            for (int nt2 = 0; nt2 < 4; nt2++) {
                uint2 bv0 = *(const uint2*)&Vc0[(kp * VSTRU + 8 * nt2 + g) * 2];
                uint2 bv1 = *(const uint2*)&Vc1[(kp * VSTRU + 8 * nt2 + g) * 2];
                mma_tf32(o[nt2], a0, bv0.x, bv0.y);
                mma_tf32(o[nt2], a1, bv1.x, bv1.y);
            }
        }

        // ---- STS tiles t0+2, t0+3 ----
        if (has_next) {
            #pragma unroll
            for (int p = 0; p < 2; p++) {
                unsigned* Kb = Ks + ((t0 + 2 + p) & 3) * KBUF;
                unsigned* Vb = Vs + ((t0 + 2 + p) & 3) * VBUF;
                *(uint4*)&Kb[tid * 4] = nk[p];
                #pragma unroll
                for (int j = 0; j < 2; j++) {
                    int u = tid + 256 * j;
                    int kp = u >> 4, fp = u & 15;
                    *(uint4*)&Vb[kp * (2 * VSTRU) + fp * 4] = nv[p][j];
                }
            }
        }
        __syncthreads();   // the one barrier per iteration
    }

    // ---- l reduction ----
    #pragma unroll
    for (int off = 1; off < 4; off <<= 1) {
        lp0 += __shfl_xor_sync(0xffffffffu, lp0, off);
        lp1 += __shfl_xor_sync(0xffffffffu, lp1, off);
    }
    if (t == 0) {
        red[nw * 64 + r0]     = lp0;
        red[nw * 64 + r0 + 8] = lp1;
    }

    // ---- O combine across nw pairs ----
    if (nw == 1) {
        #pragma unroll
        for (int nt2 = 0; nt2 < 4; nt2++) {
            int f = 8 * nt2 + 2 * t;
            *(float2*)&Osm[r0 * 32 + f]       = make_float2(o[nt2][0], o[nt2][1]);
            *(float2*)&Osm[(r0 + 8) * 32 + f] = make_float2(o[nt2][2], o[nt2][3]);
        }
    }
    __syncthreads();

    if (nw == 0) {
        float inv0 = 1.0f / (red[r0] + red[64 + r0]);
        float inv1 = 1.0f / (red[r0 + 8] + red[64 + r0 + 8]);
        int b = q0 / 4608;
        int rem = q0 - b * 4608;
        int h = rem / 576;
        int lp = (rem - h * 576) + 16 * mw + g;
        #pragma unroll
        for (int nt2 = 0; nt2 < 4; nt2++) {
            int f = 8 * nt2 + 2 * t;
            float2 pa = *(const float2*)&Osm[r0 * 32 + f];
            float2 pb = *(const float2*)&Osm[(r0 + 8) * 32 + f];
            size_t base = ((size_t)(b * 256 + h * 32 + f)) * 576;
            out[base + lp]           = (o[nt2][0] + pa.x) * inv0;
            out[base + 576 + lp]     = (o[nt2][1] + pa.y) * inv0;
            out[base + lp + 8]       = (o[nt2][2] + pb.x) * inv1;
            out[base + 576 + lp + 8] = (o[nt2][3] + pb.y) * inv1;
        }
    }
}

// ---------------------------------------------------------------------------
extern "C" void kernel_launch(void* const* d_in, const int* in_sizes, int n_in,
                              void* d_out, int out_size)
{
    const float* x  = (const float*)d_in[0];
    const float* wq = (const float*)d_in[1];
    const float* wk = (const float*)d_in[2];
    const float* wv = (const float*)d_in[3];
    float* out = (float*)d_out;

    static bool attr_set = false;
    if (!attr_set) {
        cudaFuncSetAttribute(attn_kernel,
                             cudaFuncAttributeMaxDynamicSharedMemorySize,
                             SMEM_BYTES);
        attr_set = true;
    }

    dim3 g1(16, 9, 3);
    qkv_kernel<<<g1, 256>>>(x, wq, wk, wv);
    attn_kernel<<<NTILES, 256, SMEM_BYTES>>>(out);
}

// round 16
// speedup vs baseline: 1.2480x; 1.2480x over previous
#include <cuda_runtime.h>
#include <cuda_fp16.h>
#include <math.h>

#define B_   2
#define G_   8
#define L_   576
#define D_   32
#define NTOK 9216
#define NT32 (NTOK * 32)
#define NTILES 144
#define NTILES_HALF 72
#define LOG2E 1.4426950408889634f

// Scratch (__device__ globals; allocation-free rule)
__device__ float    g_Q[NT32];
__device__ unsigned g_Kq[NT32 / 2];   // f16 K hi: [tile][kn 64][4 uint4]
__device__ unsigned g_Vp[NT32];       // tf32 V: [tile][kp 32][feat 32] uint2
__device__ float    g_qnorm2[NTOK];
__device__ int      g_kmax2;
__device__ float    g_Opart[2 * 32 * NTOK];  // [half][feat][token]
__device__ float    g_lpart[2 * NTOK];       // [half][token]

__device__ __forceinline__ unsigned f2tf32(float x) {
    unsigned r;
    asm("cvt.rna.tf32.f32 %0, %1;" : "=r"(r) : "f"(x));
    return r;
}
__device__ __forceinline__ void split2_f16(float x0, float x1,
                                           unsigned& hi, unsigned& lo) {
    __half h0 = __float2half_rn(x0), h1 = __float2half_rn(x1);
    __half l0 = __float2half_rn(x0 - __half2float(h0));
    __half l1 = __float2half_rn(x1 - __half2float(h1));
    hi = ((unsigned)__half_as_ushort(h1) << 16) | __half_as_ushort(h0);
    lo = ((unsigned)__half_as_ushort(l1) << 16) | __half_as_ushort(l0);
}
__device__ __forceinline__ void mma_f16(float c[4], const unsigned a[4],
                                        unsigned b0, unsigned b1) {
    asm volatile(
        "mma.sync.aligned.m16n8k16.row.col.f32.f16.f16.f32 "
        "{%0,%1,%2,%3}, {%4,%5,%6,%7}, {%8,%9}, {%0,%1,%2,%3};"
        : "+f"(c[0]), "+f"(c[1]), "+f"(c[2]), "+f"(c[3])
        : "r"(a[0]), "r"(a[1]), "r"(a[2]), "r"(a[3]), "r"(b0), "r"(b1));
}
__device__ __forceinline__ void mma_tf32(float c[4], const unsigned a[4],
                                         unsigned b0, unsigned b1) {
    asm volatile(
        "mma.sync.aligned.m16n8k8.row.col.f32.tf32.tf32.f32 "
        "{%0,%1,%2,%3}, {%4,%5,%6,%7}, {%8,%9}, {%0,%1,%2,%3};"
        : "+f"(c[0]), "+f"(c[1]), "+f"(c[2]), "+f"(c[3])
        : "r"(a[0]), "r"(a[1]), "r"(a[2]), "r"(a[3]), "r"(b0), "r"(b1));
}

// ---------------------------------------------------------------------------
// Kernel 1: grouped 1x1 conv, one matrix per blockIdx.z.
// Q scaled + row norms. K(+PE): f16 HI only, packed per-key, smem-staged,
// coalesced write-out. V -> tf32 paired layout.
// ---------------------------------------------------------------------------
__global__ void __launch_bounds__(256) qkv_kernel(
    const float* __restrict__ x,
    const float* __restrict__ wq,
    const float* __restrict__ wk,
    const float* __restrict__ wv)
{
    const int bh = blockIdx.x;
    const int b  = bh >> 3;
    const int h  = bh & 7;
    const int l0 = blockIdx.y * 64;
    const int m  = blockIdx.z;

    __shared__ float xs[32][64];
    __shared__ __half Ksm[64][32];   // K hi tile image (m==1 only)

    const int tid = threadIdx.x;
    const float* xbase = x + ((size_t)(b * 256 + h * 32)) * L_ + l0;
    for (int i = tid; i < 32 * 64; i += 256) {
        int dd = i >> 6, ll = i & 63;
        xs[dd][ll] = xbase[dd * L_ + ll];
    }
    __syncthreads();

    const int o    = tid & 31;
    const int lg   = (tid >> 5) * 8;
    const int c    = h * 32 + o;
    const int nbase = bh * L_ + l0 + lg;
    const int tile = bh * 9 + blockIdx.y;

    const float* w = (m == 0 ? wq : (m == 1 ? wk : wv)) + (size_t)c * 32;
    float acc[8];
    #pragma unroll
    for (int e = 0; e < 8; e++) acc[e] = 0.f;

    #pragma unroll
    for (int dd = 0; dd < 32; dd++) {
        float wv_ = w[dd];
        float4 a  = *(const float4*)&xs[dd][lg];
        float4 a2 = *(const float4*)&xs[dd][lg + 4];
        acc[0] = fmaf(wv_, a.x,  acc[0]);
        acc[1] = fmaf(wv_, a.y,  acc[1]);
        acc[2] = fmaf(wv_, a.z,  acc[2]);
        acc[3] = fmaf(wv_, a.w,  acc[3]);
        acc[4] = fmaf(wv_, a2.x, acc[4]);
        acc[5] = fmaf(wv_, a2.y, acc[5]);
        acc[6] = fmaf(wv_, a2.z, acc[6]);
        acc[7] = fmaf(wv_, a2.w, acc[7]);
    }

    if (m == 0) {
        const float scale = 0.17677669529663688f;  // 1/sqrt(32)
        #pragma unroll
        for (int e = 0; e < 8; e++) {
            float val = acc[e] * scale;
            g_Q[(size_t)(nbase + e) * 32 + o] = val;
            float sq = val * val;
            #pragma unroll
            for (int off = 16; off > 0; off >>= 1)
                sq += __shfl_xor_sync(0xffffffffu, sq, off);
            if (o == 0) g_qnorm2[nbase + e] = sq;
        }
    } else if (m == 1) {
        int ieven = c & ~1;
        float tf = (-9.210340371976184f * (float)ieven) * (1.0f / 256.0f);
        float invf = (float)exp((double)tf);
        double s0d, c0d, sid, cid;
        sincos((double)invf * (double)(l0 + lg), &s0d, &c0d);
        sincos((double)invf, &sid, &cid);
        float sB = (float)s0d, cB = (float)c0d;
        float sI = (float)sid, cI = (float)cid;
        const int ksq  = o >> 4;
        const int rr   = o & 15;
        const int tq   = (rr & 7) >> 1;
        const int hw   = rr & 1;
        const int breg = rr >> 3;
        const int hbase = tq * 8 + ksq * 4 + breg * 2 + hw;
        float kmax_local = 0.f;
        #pragma unroll
        for (int e = 0; e < 8; e++) {
            float pe = (c & 1) ? cB : sB;
            float sn = sB * cI + cB * sI;
            float cn = cB * cI - sB * sI;
            sB = sn; cB = cn;
            float val = acc[e] + pe;
            int j = lg + e;
            int kn = (j & 56) + 2 * (j & 3) + ((j >> 2) & 1);  // sigma
            Ksm[kn][hbase] = __float2half_rn(val);
            float sq = val * val;
            #pragma unroll
            for (int off = 16; off > 0; off >>= 1)
                sq += __shfl_xor_sync(0xffffffffu, sq, off);
            kmax_local = fmaxf(kmax_local, sq);
        }
        if (o == 0) atomicMax(&g_kmax2, __float_as_int(kmax_local));
        __syncthreads();
        const unsigned* src = (const unsigned*)Ksm;
        unsigned* dst = g_Kq + (size_t)tile * 1024;
        *(uint4*)&dst[tid * 4] = *(const uint4*)&src[tid * 4];
    } else {
        #pragma unroll
        for (int e = 0; e < 8; e++) {
            int j = lg + e;
            int kp   = ((j >> 3) << 2) + (j & 3);
            int slot = (j >> 2) & 1;
            g_Vp[(size_t)tile * 2048 + (size_t)(kp * 32 + o) * 2 + slot] =
                f2tf32(acc[e]);
        }
    }
}

// ---------------------------------------------------------------------------
// Kernel 2: flash attention, KV-split halves, 2 CTAs/SM. grid (144, 2),
// 256 threads, __launch_bounds__(256,2). Per-CTA structure = R15: 2 tiles/
// iter, quad-buffered, one barrier/iter; QK f16-hi (2 MMAs/chunk via Q split),
// PV tf32, P in regs. Partials to scratch; combine kernel finishes.
// ---------------------------------------------------------------------------
#define KSTR  16       // words per key row (bank-verified)
#define KBUF  1024     // 64 * 16 words
#define VSTRU 36
#define VBUF  2304     // 32 * 36 * 2 words
#define QSTR  36
#define OFF_K 0
#define OFF_V (4 * KBUF)
#define OFF_Q (OFF_V + 4 * VBUF)
#define OFF_O OFF_Q            /* Osm overlays Q staging */
#define OFF_R (OFF_Q + 64 * QSTR)
#define SMEM_WORDS (OFF_R + 128)
#define SMEM_BYTES (SMEM_WORDS * 4)

__global__ void __launch_bounds__(256, 2) attn_kernel()
{
    extern __shared__ unsigned smem[];
    unsigned* Ks  = smem + OFF_K;
    unsigned* Vs  = smem + OFF_V;
    float*    Qst = (float*)(smem + OFF_Q);
    float*    Osm = (float*)(smem + OFF_O);
    float*    red = (float*)(smem + OFF_R);

    const int tid  = threadIdx.x;
    const int lane = tid & 31;
    const int w    = tid >> 5;
    const int mw   = w >> 1, nw = w & 1;
    const int g    = lane >> 2, t = lane & 3;
    const int q0   = blockIdx.x * 64;
    const int half = blockIdx.y;
    const int tbase = half * NTILES_HALF;
    const int r0   = 16 * mw + g;

    // ---- stage Q, build f16 split A-frags ----
    for (int i = tid; i < 512; i += 256) {
        int r = i >> 3, c = (i & 7) * 4;
        *(float4*)&Qst[r * QSTR + c] =
            *(const float4*)&g_Q[(size_t)(q0 + r) * 32 + c];
    }
    __syncthreads();

    unsigned qh[2][4], ql[2][4];
    #pragma unroll
    for (int ks = 0; ks < 2; ks++) {
        int d0 = 16 * ks + 2 * t;
        split2_f16(Qst[r0 * QSTR + d0],           Qst[r0 * QSTR + d0 + 1],
                   qh[ks][0], ql[ks][0]);
        split2_f16(Qst[(r0 + 8) * QSTR + d0],     Qst[(r0 + 8) * QSTR + d0 + 1],
                   qh[ks][1], ql[ks][1]);
        split2_f16(Qst[r0 * QSTR + d0 + 8],       Qst[r0 * QSTR + d0 + 9],
                   qh[ks][2], ql[ks][2]);
        split2_f16(Qst[(r0 + 8) * QSTR + d0 + 8], Qst[(r0 + 8) * QSTR + d0 + 9],
                   qh[ks][3], ql[ks][3]);
    }

    const float kmax2 = __int_as_float(g_kmax2);
    const float Ml0 = sqrtf(g_qnorm2[q0 + r0]     * kmax2) * LOG2E;
    const float Ml1 = sqrtf(g_qnorm2[q0 + r0 + 8] * kmax2) * LOG2E;

    __syncthreads();   // Q staging reads done (Osm overlays at end)

    // ---- prefetch tiles tbase, tbase+1 into buffers 0,1 ----
    #pragma unroll
    for (int p = 0; p < 2; p++) {
        unsigned* Kb = Ks + p * KBUF;
        unsigned* Vb = Vs + p * VBUF;
        *(uint4*)&Kb[tid * 4] =
            *(const uint4*)&g_Kq[(size_t)(tbase + p) * 1024 + (size_t)tid * 4];
        #pragma unroll
        for (int j = 0; j < 2; j++) {
            int u = tid + 256 * j;
            uint4 vv = *(const uint4*)&g_Vp[(size_t)(tbase + p) * 2048 +
                                            (size_t)u * 4];
            int kp = u >> 4, fp = u & 15;
            *(uint4*)&Vb[kp * (2 * VSTRU) + fp * 4] = vv;
        }
    }
    __syncthreads();

    float o[4][4];
    #pragma unroll
    for (int i = 0; i < 4; i++)
        #pragma unroll
        for (int jj = 0; jj < 4; jj++) o[i][jj] = 0.f;
    float lp0 = 0.f, lp1 = 0.f;

    for (int it = 0; it < NTILES_HALF / 2; it++) {
        const int t0 = 2 * it;
        const unsigned* Kc0 = Ks + (t0 & 3) * KBUF;
        const unsigned* Kc1 = Ks + ((t0 + 1) & 3) * KBUF;
        const unsigned* Vc0 = Vs + (t0 & 3) * VBUF;
        const unsigned* Vc1 = Vs + ((t0 + 1) & 3) * VBUF;

        // ---- LDG tiles t0+2, t0+3 ----
        uint4 nk[2], nv[2][2];
        const bool has_next = (t0 + 2 < NTILES_HALF);
        if (has_next) {
            #pragma unroll
            for (int p = 0; p < 2; p++) {
                nk[p] = *(const uint4*)&g_Kq[(size_t)(tbase + t0 + 2 + p) * 1024 +
                                             (size_t)tid * 4];
                size_t vb = (size_t)(tbase + t0 + 2 + p) * 2048;
                #pragma unroll
                for (int j = 0; j < 2; j++) {
                    int u = tid + 256 * j;
                    nv[p][j] = *(const uint4*)&g_Vp[vb + (size_t)u * 4];
                }
            }
        }

        // ---- S for both tiles: one LDS.128 per nt feeds both k-chunks ----
        float S0[4][4], S1[4][4];
        #pragma unroll
        for (int i = 0; i < 4; i++)
            #pragma unroll
            for (int jj = 0; jj < 4; jj++) { S0[i][jj] = 0.f; S1[i][jj] = 0.f; }

        #pragma unroll
        for (int nt = 0; nt < 4; nt++) {
            int kn = 32 * nw + 8 * nt + g;
            uint4 bf0 = *(const uint4*)&Kc0[kn * KSTR + 4 * t];
            uint4 bf1 = *(const uint4*)&Kc1[kn * KSTR + 4 * t];
            mma_f16(S0[nt], qh[0], bf0.x, bf0.y);
            mma_f16(S1[nt], qh[0], bf1.x, bf1.y);
            mma_f16(S0[nt], ql[0], bf0.x, bf0.y);
            mma_f16(S1[nt], ql[0], bf1.x, bf1.y);
            mma_f16(S0[nt], qh[1], bf0.z, bf0.w);
            mma_f16(S1[nt], qh[1], bf1.z, bf1.w);
            mma_f16(S0[nt], ql[1], bf0.z, bf0.w);
            mma_f16(S1[nt], ql[1], bf1.z, bf1.w);
        }

        // ---- P = exp2(S*log2e - M) in-place; accumulate l ----
        #pragma unroll
        for (int nt = 0; nt < 4; nt++) {
            S0[nt][0] = exp2f(fmaf(S0[nt][0], LOG2E, -Ml0));
            S0[nt][1] = exp2f(fmaf(S0[nt][1], LOG2E, -Ml0));
            S0[nt][2] = exp2f(fmaf(S0[nt][2], LOG2E, -Ml1));
            S0[nt][3] = exp2f(fmaf(S0[nt][3], LOG2E, -Ml1));
            S1[nt][0] = exp2f(fmaf(S1[nt][0], LOG2E, -Ml0));
            S1[nt][1] = exp2f(fmaf(S1[nt][1], LOG2E, -Ml0));
            S1[nt][2] = exp2f(fmaf(S1[nt][2], LOG2E, -Ml1));
            S1[nt][3] = exp2f(fmaf(S1[nt][3], LOG2E, -Ml1));
            lp0 += S0[nt][0] + S0[nt][1] + S1[nt][0] + S1[nt][1];
            lp1 += S0[nt][2] + S0[nt][3] + S1[nt][2] + S1[nt][3];
        }

        // ---- O += P V for both tiles (tf32 single-pass) ----
        #pragma unroll
        for (int ks = 0; ks < 4; ks++) {
            unsigned a0[4], a1[4];
            a0[0] = f2tf32(S0[ks][0]);  a1[0] = f2tf32(S1[ks][0]);
            a0[1] = f2tf32(S0[ks][2]);  a1[1] = f2tf32(S1[ks][2]);
            a0[2] = f2tf32(S0[ks][1]);  a1[2] = f2tf32(S1[ks][1]);
            a0[3] = f2tf32(S0[ks][3]);  a1[3] = f2tf32(S1[ks][3]);
            int kp = (4 * nw + ks) * 4 + t;
            #pragma unroll
            for (int nt2 = 0; nt2 < 4; nt2++) {
                uint2 bv0 = *(const uint2*)&Vc0[(kp * VSTRU + 8 * nt2 + g) * 2];
                uint2 bv1 = *(const uint2*)&Vc1[(kp * VSTRU + 8 * nt2 + g) * 2];
                mma_tf32(o[nt2], a0, bv0.x, bv0.y);
                mma_tf32(o[nt2], a1, bv1.x, bv1.y);
            }
        }

        // ---- STS tiles t0+2, t0+3 ----
        if (has_next) {
            #pragma unroll
            for (int p = 0; p < 2; p++) {
                unsigned* Kb = Ks + ((t0 + 2 + p) & 3) * KBUF;
                unsigned* Vb = Vs + ((t0 + 2 + p) & 3) * VBUF;
                *(uint4*)&Kb[tid * 4] = nk[p];
                #pragma unroll
                for (int j = 0; j < 2; j++) {
                    int u = tid + 256 * j;
                    int kp = u >> 4, fp = u & 15;
                    *(uint4*)&Vb[kp * (2 * VSTRU) + fp * 4] = nv[p][j];
                }
            }
        }
        __syncthreads();   // the one barrier per iteration
    }

    // ---- l reduction ----
    #pragma unroll
    for (int off = 1; off < 4; off <<= 1) {
        lp0 += __shfl_xor_sync(0xffffffffu, lp0, off);
        lp1 += __shfl_xor_sync(0xffffffffu, lp1, off);
    }
    if (t == 0) {
        red[nw * 64 + r0]     = lp0;
        red[nw * 64 + r0 + 8] = lp1;
    }

    // ---- O combine across nw pairs (Osm overlays Qst) ----
    if (nw == 1) {
        #pragma unroll
        for (int nt2 = 0; nt2 < 4; nt2++) {
            int f = 8 * nt2 + 2 * t;
            *(float2*)&Osm[r0 * 32 + f]       = make_float2(o[nt2][0], o[nt2][1]);
            *(float2*)&Osm[(r0 + 8) * 32 + f] = make_float2(o[nt2][2], o[nt2][3]);
        }
    }
    __syncthreads();

    if (nw == 0) {
        float* Op = g_Opart + (size_t)half * (32 * NTOK);
        #pragma unroll
        for (int nt2 = 0; nt2 < 4; nt2++) {
            int f = 8 * nt2 + 2 * t;
            float2 pa = *(const float2*)&Osm[r0 * 32 + f];
            float2 pb = *(const float2*)&Osm[(r0 + 8) * 32 + f];
            Op[(size_t)f * NTOK + q0 + r0]           = o[nt2][0] + pa.x;
            Op[(size_t)(f + 1) * NTOK + q0 + r0]     = o[nt2][1] + pa.y;
            Op[(size_t)f * NTOK + q0 + r0 + 8]       = o[nt2][2] + pb.x;
            Op[(size_t)(f + 1) * NTOK + q0 + r0 + 8] = o[nt2][3] + pb.y;
        }
        if (t == 0) {
            g_lpart[half * NTOK + q0 + r0]     = red[r0] + red[64 + r0];
            g_lpart[half * NTOK + q0 + r0 + 8] = red[r0 + 8] + red[64 + r0 + 8];
        }
    }
}

// ---------------------------------------------------------------------------
// Kernel 3: combine halves, normalize, scatter to NCHW. grid (36, 32).
// ---------------------------------------------------------------------------
__global__ void __launch_bounds__(256) combine_kernel(float* __restrict__ out)
{
    const int n = blockIdx.x * 256 + threadIdx.x;   // token
    const int f = blockIdx.y;                       // feat
    float l = g_lpart[n] + g_lpart[NTOK + n];
    float v = g_Opart[(size_t)f * NTOK + n] +
              g_Opart[(size_t)(32 * NTOK) + (size_t)f * NTOK + n];
    int b = n / 4608;
    int rem = n - b * 4608;
    int h = rem / 576;
    int lpos = rem - h * 576;
    out[((size_t)(b * 256 + h * 32 + f)) * 576 + lpos] = v / l;
}

// ---------------------------------------------------------------------------
extern "C" void kernel_launch(void* const* d_in, const int* in_sizes, int n_in,
                              void* d_out, int out_size)
{
    const float* x  = (const float*)d_in[0];
    const float* wq = (const float*)d_in[1];
    const float* wk = (const float*)d_in[2];
    const float* wv = (const float*)d_in[3];
    float* out = (float*)d_out;

    static bool attr_set = false;
    if (!attr_set) {
        cudaFuncSetAttribute(attn_kernel,
                             cudaFuncAttributeMaxDynamicSharedMemorySize,
                             SMEM_BYTES);
        attr_set = true;
    }

    dim3 g1(16, 9, 3);
    qkv_kernel<<<g1, 256>>>(x, wq, wk, wv);
    dim3 g2(NTOK / 64, 2);
    attn_kernel<<<g2, 256, SMEM_BYTES>>>();
    dim3 g3(NTOK / 256, 32);
    combine_kernel<<<g3, 256>>>(out);
}